// round 7
// baseline (speedup 1.0000x reference)
#include <cuda_runtime.h>

// ApsUp: polyphase 2x upsample + circular pad + depthwise 3x3 binomial blur,
// collapsed to a direct gather (only one of 4 phases is nonzero per batch).
//
// Shapes (fixed): inp [16,256,64,64] f32, poly [16] i32, out [16,256,128,128] f32.
//
// Regime: HBM-wall (335.5 MB compulsory traffic, ~6.6 TB/s achieved). This
// round uses Blackwell 256-bit stores (st.global.cs.v8.f32 -> STG.256): each
// lane emits one 32B store of 8 consecutive output cols of one output row.
//
// Warp owns input row pair A -> output rows 2A, 2A+1.
//   lane L: group s = L>>4 (0: row 2A+r from row A only; 1: row 2A+1-r from
//   rows A and a1), tile t = L&15 -> output cols 8t..8t+7.
//   Input: float4 at col 4t (group 1 also from row a1). Circular col wrap via
//   warp shuffle within the 16-lane group (16 lanes x 4 cols = 64 = N).

#define B_ 16
#define C_ 256
#define N_ 64
#define TWO_N 128

__global__ __launch_bounds__(256) void aps_up_kernel(
    const float* __restrict__ inp,
    const int*   __restrict__ poly,
    float*       __restrict__ out)
{
    // blockIdx.x = bc*8 + g ; warp w handles row pair A = g*8 + w
    const int bc = blockIdx.x >> 3;
    const int g  = blockIdx.x & 7;
    const int w  = threadIdx.x >> 5;
    const int L  = threadIdx.x & 31;
    const int A  = g * 8 + w;
    const int bb = bc >> 8;

    const int s = L >> 4;                 // 0: "even" row (weight .5 on A)
    const int t = L & 15;                 // col tile: input float4 at col 4t

    const int p = __ldg(&poly[bb]);
    const int r = p & 1;                  // row phase offset (warp-uniform)
    const int c = p >> 1;                 // col phase offset (warp-uniform)

    const int a1 = (A + (r ? (N_ - 1) : 1)) & (N_ - 1);

    const float* base = inp + (size_t)bc * (N_ * N_);
    const float4 a = *reinterpret_cast<const float4*>(base + A * N_ + 4 * t);
    float4 b = make_float4(0.f, 0.f, 0.f, 0.f);
    if (s) b = *reinterpret_cast<const float4*>(base + a1 * N_ + 4 * t);

    // Vertical combine with folded weights:
    //   s==0 -> v[j] = 0.5  * A[j]          (output row 2A + r)
    //   s==1 -> v[j] = 0.25 * (A[j]+a1[j])  (output row 2A + 1 - r)
    const float wa = s ? 0.25f : 0.5f;
    const float wb = s ? 0.25f : 0.0f;
    float v0 = wa * a.x + wb * b.x;
    float v1 = wa * a.y + wb * b.y;
    float v2 = wa * a.z + wb * b.z;
    float v3 = wa * a.w + wb * b.w;

    const unsigned m = 0xFFFFFFFFu;
    float o0, o1, o2, o3, o4, o5, o6, o7;
    if (c == 0) {
        // need v[4t+4] = next lane's v0 (circular within 16-lane group)
        const float v4 = __shfl_sync(m, v0, (L & 16) | ((t + 1) & 15));
        o0 = 0.5f  *  v0;
        o1 = 0.25f * (v0 + v1);
        o2 = 0.5f  *  v1;
        o3 = 0.25f * (v1 + v2);
        o4 = 0.5f  *  v2;
        o5 = 0.25f * (v2 + v3);
        o6 = 0.5f  *  v3;
        o7 = 0.25f * (v3 + v4);
    } else {
        // need v[4t-1] = prev lane's v3 (circular within 16-lane group)
        const float vm = __shfl_sync(m, v3, (L & 16) | ((t + 15) & 15));
        o0 = 0.25f * (vm + v0);
        o1 = 0.5f  *  v0;
        o2 = 0.25f * (v0 + v1);
        o3 = 0.5f  *  v1;
        o4 = 0.25f * (v1 + v2);
        o5 = 0.5f  *  v2;
        o6 = 0.25f * (v2 + v3);
        o7 = 0.5f  *  v3;
    }

    const int rowIdx = s ? (2 * A + 1 - r) : (2 * A + r);
    float* op = out + (size_t)bc * (TWO_N * TWO_N)
                    + (size_t)rowIdx * TWO_N + 8 * t;

    // Blackwell 256-bit streaming store (STG.256), 32B-aligned by construction.
    asm volatile(
        "st.global.cs.v8.f32 [%0], {%1, %2, %3, %4, %5, %6, %7, %8};"
        :: "l"(op),
           "f"(o0), "f"(o1), "f"(o2), "f"(o3),
           "f"(o4), "f"(o5), "f"(o6), "f"(o7)
        : "memory");
}

extern "C" void kernel_launch(void* const* d_in, const int* in_sizes, int n_in,
                              void* d_out, int out_size)
{
    const float* inp  = (const float*)d_in[0];
    const int*   poly = (const int*)d_in[1];
    float*       out  = (float*)d_out;

    // 4096 channels * 8 blocks each (8 warps/block, 1 warp per row pair)
    aps_up_kernel<<<B_ * C_ * 8, 256>>>(inp, poly, out);
}